// round 9
// baseline (speedup 1.0000x reference)
#include <cuda_runtime.h>
#include <cstdint>

#define S_LEN   2048
#define BATCH   16
#define HID     512
#define IN_DIM  128
#define OUT_DIM 128
#define NCTA    128
#define JS      4
#define HP      520

// ---- scratch: device globals only ----
__device__ float g_pz [(size_t)BATCH * S_LEN * HID];
__device__ float g_pr [(size_t)BATCH * S_LEN * HID];
__device__ float g_y1 [(size_t)BATCH * S_LEN * HID];
__device__ float g_h0v[BATCH * HID];
__device__ float g_h1v[BATCH * HID];
__device__ float g_rh0[BATCH * HID];
__device__ float g_rh1[BATCH * HID];
__device__ unsigned int g_ctr  [128];  // arrival counters: 4 lines (0,32,64,96)
__device__ unsigned int g_epoch[128];  // broadcast epochs:  4 lines (0,32,64,96)

// Two-line grid barrier: arrivals RMW the counter line; last arriver publishes
// the round to a SEPARATE epoch line; waiters poll epoch with pure loads, so
// polling traffic never contends with the counter's LTS atomic ALU.
__device__ __forceinline__ void bar_arrive(unsigned int* ctr, unsigned int* ep,
                                           unsigned int target) {
    unsigned int old;
    asm volatile("atom.acq_rel.gpu.global.add.u32 %0, [%1], %2;"
                 : "=r"(old) : "l"(ctr), "r"(1u) : "memory");
    if (old == target - 1u)
        asm volatile("st.release.gpu.global.u32 [%0], %1;"
                     :: "l"(ep), "r"(target) : "memory");
}
__device__ __forceinline__ void bar_wait(unsigned int* ep, unsigned int target) {
    unsigned int v;
    do { asm volatile("ld.acquire.gpu.global.u32 %0, [%1];"
                      : "=r"(v) : "l"(ep) : "memory"); }
    while (v < target);
}
__device__ __forceinline__ void ffma2(unsigned long long& d,
                                      unsigned long long a, unsigned long long b) {
    asm volatile("fma.rn.f32x2 %0, %1, %2, %0;" : "+l"(d) : "l"(a), "l"(b));
}
__device__ __forceinline__ float hsum2(unsigned long long a) {
    return __uint_as_float((unsigned)a) + __uint_as_float((unsigned)(a >> 32));
}
__device__ __forceinline__ void barg(int id) {
    asm volatile("bar.sync %0, 256;" :: "r"(id) : "memory");
}

__global__ void init_kernel(const float* __restrict__ hst) {
    int i = blockIdx.x * blockDim.x + threadIdx.x;
    if (i < 128) { g_ctr[i] = 0; g_epoch[i] = 0; }
    if (i < BATCH * HID) {
        int b = i >> 9, j = i & 511;
        g_h0v[i] = hst[(b << 10) + j];
        g_h1v[i] = hst[(b << 10) + 512 + j];
    }
}

// C[M,N] = A[M,K] @ B[N,K]^T (+bias). 128x128 tile, BK=16, 8x8 microtile.
__global__ __launch_bounds__(256, 2) void gemm_abt_kernel(
    const float* __restrict__ A, const float* __restrict__ B,
    const float* __restrict__ bias, float* __restrict__ C,
    int M, int N, int K)
{
    __shared__ __align__(16) float As[16][132];
    __shared__ __align__(16) float Bs[16][132];
    const int t = threadIdx.x, tx = t & 15, ty = t >> 4;
    const int m0 = blockIdx.y * 128, n0 = blockIdx.x * 128;
    const float* Ab = A + (size_t)m0 * K;
    const float* Bb = B + (size_t)n0 * K;

    float acc[8][8];
#pragma unroll
    for (int i = 0; i < 8; i++)
#pragma unroll
        for (int j = 0; j < 8; j++) acc[i][j] = 0.0f;

    for (int k0 = 0; k0 < K; k0 += 16) {
#pragma unroll
        for (int u = 0; u < 2; u++) {
            int f = t + 256 * u, r = f >> 2, c4 = f & 3;
            float4 va = *(const float4*)(Ab + (size_t)r * K + k0 + c4 * 4);
            As[c4*4+0][r] = va.x; As[c4*4+1][r] = va.y;
            As[c4*4+2][r] = va.z; As[c4*4+3][r] = va.w;
            float4 vb = *(const float4*)(Bb + (size_t)r * K + k0 + c4 * 4);
            Bs[c4*4+0][r] = vb.x; Bs[c4*4+1][r] = vb.y;
            Bs[c4*4+2][r] = vb.z; Bs[c4*4+3][r] = vb.w;
        }
        __syncthreads();
#pragma unroll
        for (int k = 0; k < 16; k++) {
            float rm[8], rn[8];
            *(float4*)&rm[0] = *(const float4*)&As[k][ty*8];
            *(float4*)&rm[4] = *(const float4*)&As[k][ty*8+4];
            *(float4*)&rn[0] = *(const float4*)&Bs[k][tx*8];
            *(float4*)&rn[4] = *(const float4*)&Bs[k][tx*8+4];
#pragma unroll
            for (int i = 0; i < 8; i++)
#pragma unroll
                for (int j = 0; j < 8; j++)
                    acc[i][j] = fmaf(rm[i], rn[j], acc[i][j]);
        }
        __syncthreads();
    }
    float bv[8];
#pragma unroll
    for (int j = 0; j < 8; j++) bv[j] = bias ? bias[n0 + tx*8 + j] : 0.0f;
#pragma unroll
    for (int i = 0; i < 8; i++) {
        float* cp = C + (size_t)(m0 + ty*8 + i) * N + n0 + tx*8;
        float4 o0, o1;
        o0.x = acc[i][0]+bv[0]; o0.y = acc[i][1]+bv[1];
        o0.z = acc[i][2]+bv[2]; o0.w = acc[i][3]+bv[3];
        o1.x = acc[i][4]+bv[4]; o1.y = acc[i][5]+bv[5];
        o1.z = acc[i][6]+bv[6]; o1.w = acc[i][7]+bv[7];
        *(float4*)cp = o0; *(float4*)(cp+4) = o1;
    }
}

// ---- gang matvec map: 8 warps (256 thr) per gang ----
// lane: jw=lane&3, ksub=lane>>2; warp w8(0..7): bq=w8>>1, khi=w8&1.
__device__ __forceinline__ void mv_quad(const float* __restrict__ T,
    const float* __restrict__ w0, const float* __restrict__ w1,
    const float* __restrict__ w2, const float* __restrict__ w3,
    float* q0, float* q1, float* q2, float* q3,
    int jw, int ksub, int bq, int khi, int fbase)
{
    unsigned long long a0[4]={0,0,0,0}, a1[4]={0,0,0,0},
                       a2[4]={0,0,0,0}, a3[4]={0,0,0,0};
#pragma unroll
    for (int kk = 0; kk < 8; kk++) {
        const int fo = (fbase + 16*kk) * 4;
        ulonglong2 wa = *(const ulonglong2*)&w0[jw*HP + fo];
        ulonglong2 wb = *(const ulonglong2*)&w1[jw*HP + fo];
        ulonglong2 wc = *(const ulonglong2*)&w2[jw*HP + fo];
        ulonglong2 wd = *(const ulonglong2*)&w3[jw*HP + fo];
#pragma unroll
        for (int i = 0; i < 4; i++) {
            ulonglong2 hv = *(const ulonglong2*)&T[(bq*4+i)*HP + fo];
            ffma2(a0[i], hv.x, wa.x); ffma2(a0[i], hv.y, wa.y);
            ffma2(a1[i], hv.x, wb.x); ffma2(a1[i], hv.y, wb.y);
            ffma2(a2[i], hv.x, wc.x); ffma2(a2[i], hv.y, wc.y);
            ffma2(a3[i], hv.x, wd.x); ffma2(a3[i], hv.y, wd.y);
        }
    }
    float s0[4], s1[4], s2[4], s3[4];
#pragma unroll
    for (int i = 0; i < 4; i++) {
        s0[i]=hsum2(a0[i]); s1[i]=hsum2(a1[i]); s2[i]=hsum2(a2[i]); s3[i]=hsum2(a3[i]);
    }
#pragma unroll
    for (int off = 4; off < 32; off <<= 1)
#pragma unroll
        for (int i = 0; i < 4; i++) {
            s0[i] += __shfl_xor_sync(0xffffffffu, s0[i], off);
            s1[i] += __shfl_xor_sync(0xffffffffu, s1[i], off);
            s2[i] += __shfl_xor_sync(0xffffffffu, s2[i], off);
            s3[i] += __shfl_xor_sync(0xffffffffu, s3[i], off);
        }
    if (ksub == 0)
#pragma unroll
        for (int i = 0; i < 4; i++) {
            int o = khi*64 + (bq*4+i)*4 + jw;
            q0[o] = s0[i]; q1[o] = s1[i]; q2[o] = s2[i]; q3[o] = s3[i];
        }
}
__device__ __forceinline__ void mv_pair(const float* __restrict__ T,
    const float* __restrict__ w0, const float* __restrict__ w1,
    float* q0, float* q1, int jw, int ksub, int bq, int khi, int fbase)
{
    unsigned long long a0[4]={0,0,0,0}, a1[4]={0,0,0,0};
#pragma unroll
    for (int kk = 0; kk < 8; kk++) {
        const int fo = (fbase + 16*kk) * 4;
        ulonglong2 wa = *(const ulonglong2*)&w0[jw*HP + fo];
        ulonglong2 wb = *(const ulonglong2*)&w1[jw*HP + fo];
#pragma unroll
        for (int i = 0; i < 4; i++) {
            ulonglong2 hv = *(const ulonglong2*)&T[(bq*4+i)*HP + fo];
            ffma2(a0[i], hv.x, wa.x); ffma2(a0[i], hv.y, wa.y);
            ffma2(a1[i], hv.x, wb.x); ffma2(a1[i], hv.y, wb.y);
        }
    }
    float s0[4], s1[4];
#pragma unroll
    for (int i = 0; i < 4; i++) { s0[i]=hsum2(a0[i]); s1[i]=hsum2(a1[i]); }
#pragma unroll
    for (int off = 4; off < 32; off <<= 1)
#pragma unroll
        for (int i = 0; i < 4; i++) {
            s0[i] += __shfl_xor_sync(0xffffffffu, s0[i], off);
            s1[i] += __shfl_xor_sync(0xffffffffu, s1[i], off);
        }
    if (ksub == 0)
#pragma unroll
        for (int i = 0; i < 4; i++) {
            int o = khi*64 + (bq*4+i)*4 + jw;
            q0[o] = s0[i]; q1[o] = s1[i];
        }
}
__device__ __forceinline__ void mv_one(const float* __restrict__ T,
    const float* __restrict__ w0, float* q0,
    int jw, int ksub, int bq, int khi, int fbase)
{
    unsigned long long a0[4]={0,0,0,0};
#pragma unroll
    for (int kk = 0; kk < 8; kk++) {
        const int fo = (fbase + 16*kk) * 4;
        ulonglong2 wa = *(const ulonglong2*)&w0[jw*HP + fo];
#pragma unroll
        for (int i = 0; i < 4; i++) {
            ulonglong2 hv = *(const ulonglong2*)&T[(bq*4+i)*HP + fo];
            ffma2(a0[i], hv.x, wa.x); ffma2(a0[i], hv.y, wa.y);
        }
    }
    float s0[4];
#pragma unroll
    for (int i = 0; i < 4; i++) s0[i] = hsum2(a0[i]);
#pragma unroll
    for (int off = 4; off < 32; off <<= 1)
#pragma unroll
        for (int i = 0; i < 4; i++)
            s0[i] += __shfl_xor_sync(0xffffffffu, s0[i], off);
    if (ksub == 0)
#pragma unroll
        for (int i = 0; i < 4; i++)
            q0[khi*64 + (bq*4+i)*4 + jw] = s0[i];
}
__device__ __forceinline__ float q2sum(const float* q, int idx) {
    return q[idx] + q[64+idx];
}
__device__ __forceinline__ void load_tile256(float* T, const float* g, int gtid) {
#pragma unroll
    for (int u = 0; u < 8; u++) {
        int f = gtid + 256*u, b = f >> 7, c = f & 127;
        float4 v = __ldcg((const float4*)g + f);
        *(float4*)&T[b*HP + c*4] = v;
    }
}

// ---- warp-specialized 2-layer GRU: gang0 = layer0 + L1 projections, gang1 = layer1 ----
__global__ __launch_bounds__(512, 1) void gru_ws_kernel(
    const float* __restrict__ pz0, const float* __restrict__ pr0,
    const float* __restrict__ Whz0, const float* __restrict__ bhz0,
    const float* __restrict__ Whr0, const float* __restrict__ bhr0,
    const float* __restrict__ Wxz1, const float* __restrict__ Whz1,
    const float* __restrict__ bhz1, const float* __restrict__ Wxr1,
    const float* __restrict__ Whr1, const float* __restrict__ bhr1,
    float* __restrict__ hf)
{
    extern __shared__ float sm[];
    float* T0   = sm;                  // [16][HP] gang0 tile (h0 / rh0)
    float* T1   = T0 + BATCH*HP;       // [16][HP] gang1 tile (h1 / rh1)
    float* wz0  = T1 + BATCH*HP;       // 6 weight slices [4][HP]
    float* wr0  = wz0 + JS*HP;
    float* wz1  = wr0 + JS*HP;
    float* wr1  = wz1 + JS*HP;
    float* wxz  = wr1 + JS*HP;
    float* wxr  = wxz + JS*HP;
    float* q0   = wxr + JS*HP;         // partials [128] x6
    float* q1   = q0 + 128;
    float* q2   = q1 + 128;
    float* q3   = q2 + 128;
    float* q4   = q3 + 128;
    float* q5   = q4 + 128;
    float* z0s  = q5 + 128;            // [64] each
    float* h0s  = z0s + 64;
    float* xz0s = h0s + 64;
    float* xr0s = xz0s + 64;
    float* z1s  = xr0s + 64;
    float* h1s  = z1s + 64;
    float* axrs = h1s + 64;
    float* axr2 = axrs + 64;           // [2][64] double-buffered handoff
    float* axz2 = axr2 + 128;          // [2][64]
    float* bz0  = axz2 + 128;          // [4] each
    float* br0  = bz0 + 4;
    float* bz1  = br0 + 4;
    float* br1  = bz1 + 4;
    volatile int* flags = (volatile int*)(br1 + 4);  // [0]=l0_axr_done, [1]=l1_done

    const int tid  = threadIdx.x;
    const int gang = tid >> 8;
    const int gtid = tid & 255;
    const int j0   = blockIdx.x * JS;
    const int lane = tid & 31;
    const int w8   = (tid >> 5) & 7;
    const int jw = lane & 3, ksub = lane >> 2;
    const int bq = w8 >> 1, khi = w8 & 1;
    const int fbase = ksub + 8 * khi;

    for (int idx = tid; idx < JS * HID; idx += 512) {
        int jj = idx >> 9, k = idx & 511;
        size_t w = (size_t)(j0 + jj) * HID + k;
        int s = jj * HP + k;
        wz0[s] = Whz0[w]; wr0[s] = Whr0[w];
        wz1[s] = Whz1[w]; wr1[s] = Whr1[w];
        wxz[s] = Wxz1[w]; wxr[s] = Wxr1[w];
    }
    if (tid < JS) {
        bz0[tid] = bhz0[j0+tid]; br0[tid] = bhr0[j0+tid];
        bz1[tid] = bhz1[j0+tid]; br1[tid] = bhr1[j0+tid];
    }
    if (tid == 0) { flags[0] = 0; flags[1] = 0; }
    __syncthreads();

    unsigned int* C_RH0 = &g_ctr[0];   unsigned int* E_RH0 = &g_epoch[0];
    unsigned int* C_H0  = &g_ctr[32];  unsigned int* E_H0  = &g_epoch[32];
    unsigned int* C_RH1 = &g_ctr[64];  unsigned int* E_RH1 = &g_epoch[64];
    unsigned int* C_H1  = &g_ctr[96];  unsigned int* E_H1  = &g_epoch[96];

    if (gang == 0) {
        // ================= layer 0 + layer-1 input projections =================
        unsigned int tgt = NCTA;
        for (int t = 0; t <= S_LEN; t++) {
            // phase A: T0 <- h0 (== y0[t-1]); quad matvec wr0,wz0,wxr,wxz
            load_tile256(T0, g_h0v, gtid);
            if (t < S_LEN && gtid < BATCH) {
                size_t off = ((size_t)(gtid * S_LEN + t) << 9) + j0;
                *(float4*)&xz0s[gtid*4] = *(const float4*)(pz0 + off);
                *(float4*)&xr0s[gtid*4] = *(const float4*)(pr0 + off);
            }
            barg(1);
            mv_quad(T0, wr0, wz0, wxr, wxz, q0, q1, q2, q3,
                    jw, ksub, bq, khi, fbase);
            barg(1);
            if (gtid < 64) {
                const int b = gtid >> 2, jj = gtid & 3;
                if (t >= 1) {
                    while (flags[1] < t - 2) { }
                    axr2[(t&1)*64 + gtid] = q2sum(q2, gtid);
                    axz2[(t&1)*64 + gtid] = q2sum(q3, gtid);
                }
                if (t < S_LEN) {
                    float pr = q2sum(q0, gtid) + xr0s[gtid] + br0[jj];
                    float pz = q2sum(q1, gtid) + xz0s[gtid] + bz0[jj];
                    float r  = 1.0f / (1.0f + __expf(-pr));
                    z0s[gtid] = 1.0f / (1.0f + __expf(-pz));
                    float ho = T0[b*HP + j0 + jj];
                    h0s[gtid] = ho;
                    __stcg(&g_rh0[(b << 9) + j0 + jj], r * ho);
                }
            }
            barg(1);
            if (gtid == 0) {
                if (t >= 1) { __threadfence_block(); flags[0] = t; }
                if (t < S_LEN) bar_arrive(C_RH0, E_RH0, tgt);
            }
            if (t == S_LEN) break;

            // phase B: g0, h0_new
            if (gtid == 0) bar_wait(E_RH0, tgt);
            barg(1);
            load_tile256(T0, g_rh0, gtid);
            barg(1);
            mv_one(T0, wr0, q0, jw, ksub, bq, khi, fbase);
            barg(1);
            if (gtid < 64) {
                const int b = gtid >> 2, jj = gtid & 3;
                float pg = q2sum(q0, gtid) + xr0s[gtid] + br0[jj];
                float g  = tanhf(pg);
                float z  = z0s[gtid];
                float hn = z * h0s[gtid] + (1.0f - z) * g;
                __stcg(&g_h0v[(b << 9) + j0 + jj], hn);    // == y0[t]
                if (t == S_LEN - 1) hf[(b << 10) + j0 + jj] = hn;
            }
            barg(1);
            if (gtid == 0) { bar_arrive(C_H0, E_H0, tgt); bar_wait(E_H0, tgt); }
            tgt += NCTA;
            barg(1);
        }
    } else {
        // ================= layer 1 (GRU step s = t-1) =================
        unsigned int tgt = NCTA;
        for (int t = 1; t <= S_LEN; t++) {
            load_tile256(T1, g_h1v, gtid);
            barg(2);
            mv_pair(T1, wr1, wz1, q4, q5, jw, ksub, bq, khi, fbase);
            barg(2);
            if (gtid < 64) {
                const int b = gtid >> 2, jj = gtid & 3;
                while (flags[0] < t) { }
                __threadfence_block();
                float axr = axr2[(t&1)*64 + gtid];
                float axz = axz2[(t&1)*64 + gtid];
                float pr = q2sum(q4, gtid) + axr + br1[jj];
                float pz = q2sum(q5, gtid) + axz + bz1[jj];
                float r  = 1.0f / (1.0f + __expf(-pr));
                z1s[gtid] = 1.0f / (1.0f + __expf(-pz));
                float ho = T1[b*HP + j0 + jj];
                h1s[gtid] = ho; axrs[gtid] = axr;
                __stcg(&g_rh1[(b << 9) + j0 + jj], r * ho);
            }
            barg(2);
            if (gtid == 0) {
                flags[1] = t;
                bar_arrive(C_RH1, E_RH1, tgt); bar_wait(E_RH1, tgt);
            }
            barg(2);
            load_tile256(T1, g_rh1, gtid);
            barg(2);
            mv_one(T1, wr1, q4, jw, ksub, bq, khi, fbase);
            barg(2);
            if (gtid < 64) {
                const int b = gtid >> 2, jj = gtid & 3;
                float pg = q2sum(q4, gtid) + axrs[gtid] + br1[jj];
                float g  = tanhf(pg);
                float z  = z1s[gtid];
                float hn = z * h1s[gtid] + (1.0f - z) * g;
                __stcg(&g_h1v[(b << 9) + j0 + jj], hn);
                g_y1[((size_t)(b * S_LEN + (t-1)) << 9) + j0 + jj] = hn;
                if (t == S_LEN) hf[(b << 10) + 512 + j0 + jj] = hn;
            }
            barg(2);
            if (gtid == 0) { bar_arrive(C_H1, E_H1, tgt); bar_wait(E_H1, tgt); }
            tgt += NCTA;
            barg(2);
        }
    }
}

extern "C" void kernel_launch(void* const* d_in, const int* in_sizes, int n_in,
                              void* d_out, int out_size)
{
    (void)in_sizes; (void)n_in; (void)out_size;
    const float* x    = (const float*)d_in[0];
    const float* hst  = (const float*)d_in[1];
    const float* Wxz0 = (const float*)d_in[2];
    const float* Whz0 = (const float*)d_in[3];
    const float* bhz0 = (const float*)d_in[4];
    const float* Wxr0 = (const float*)d_in[5];
    const float* Whr0 = (const float*)d_in[6];
    const float* bhr0 = (const float*)d_in[7];
    const float* Wxz1 = (const float*)d_in[8];
    const float* Whz1 = (const float*)d_in[9];
    const float* bhz1 = (const float*)d_in[10];
    const float* Wxr1 = (const float*)d_in[11];
    const float* Whr1 = (const float*)d_in[12];
    const float* bhr1 = (const float*)d_in[13];
    const float* Why  = (const float*)d_in[14];
    const float* by   = (const float*)d_in[15];
    float* out = (float*)d_out;

    float *pz, *pr, *y1;
    cudaGetSymbolAddress((void**)&pz, g_pz);
    cudaGetSymbolAddress((void**)&pr, g_pr);
    cudaGetSymbolAddress((void**)&y1, g_y1);

    const int GRU_SMEM = (2*BATCH*HP + 6*JS*HP + 6*128 + 7*64 + 2*128 + 16 + 8) * 4;
    cudaFuncSetAttribute(gru_ws_kernel,
                         cudaFuncAttributeMaxDynamicSharedMemorySize, GRU_SMEM);

    const int M = BATCH * S_LEN;                        // 32768
    float* hf = out + (size_t)BATCH * S_LEN * OUT_DIM;  // h_final [B,2,H]

    // layer-0 input projections (K = 128), off the critical path
    gemm_abt_kernel<<<dim3(HID/128, M/128), 256>>>(x, Wxz0, nullptr, pz, M, HID, IN_DIM);
    gemm_abt_kernel<<<dim3(HID/128, M/128), 256>>>(x, Wxr0, nullptr, pr, M, HID, IN_DIM);
    init_kernel<<<32, 256>>>(hst);

    // warp-specialized pipelined recurrence
    gru_ws_kernel<<<NCTA, 512, GRU_SMEM>>>(pz, pr,
        Whz0, bhz0, Whr0, bhr0,
        Wxz1, Whz1, bhz1, Wxr1, Whr1, bhr1, hf);

    // output head: out = y1 @ Why^T + by
    gemm_abt_kernel<<<dim3(OUT_DIM/128, M/128), 256>>>(y1, Why, by, out, M, OUT_DIM, HID);
}

// round 10
// speedup vs baseline: 1.3698x; 1.3698x over previous
#include <cuda_runtime.h>
#include <cstdint>

#define S_LEN   2048
#define BATCH   16
#define HID     512
#define IN_DIM  128
#define OUT_DIM 128
#define NPIPE   4
#define PCTAS   32          // CTAs per pipeline
#define BL      4           // batches per pipeline
#define JSL     16          // j-dims per CTA
#define HPW     516         // weight row stride (516 % 32 == 4 -> conflict-free)
#define HPT     516         // tile row stride

// ---- scratch: device globals only ----
__device__ float g_pz [(size_t)BATCH * S_LEN * HID];
__device__ float g_pr [(size_t)BATCH * S_LEN * HID];
__device__ float g_y1 [(size_t)BATCH * S_LEN * HID];
__device__ float g_h0v[BATCH * HID];
__device__ float g_h1v[BATCH * HID];
__device__ float g_rh0[BATCH * HID];
__device__ float g_rh1[BATCH * HID];
__device__ unsigned int g_ctr[16 * 32];   // 16 counters, 128B apart

// R8-proven barrier: fire-and-forget release-add; waiter polls same line.
__device__ __forceinline__ void ctr_rel(unsigned int* p) {
    asm volatile("red.release.gpu.add.u32 [%0], %1;" :: "l"(p), "r"(1u) : "memory");
}
__device__ __forceinline__ void ctr_poll(unsigned int* p, unsigned int target) {
    unsigned int v;
    do { asm volatile("ld.acquire.gpu.u32 %0, [%1];" : "=r"(v) : "l"(p) : "memory"); }
    while (v < target);
}
__device__ __forceinline__ void ffma2(unsigned long long& d,
                                      unsigned long long a, unsigned long long b) {
    asm volatile("fma.rn.f32x2 %0, %1, %2, %0;" : "+l"(d) : "l"(a), "l"(b));
}
__device__ __forceinline__ float hsum2(unsigned long long a) {
    return __uint_as_float((unsigned)a) + __uint_as_float((unsigned)(a >> 32));
}
__device__ __forceinline__ void barg(int id) {
    asm volatile("bar.sync %0, 256;" :: "r"(id) : "memory");
}

__global__ void init_kernel(const float* __restrict__ hst) {
    int i = blockIdx.x * blockDim.x + threadIdx.x;
    if (i < 16 * 32) g_ctr[i] = 0;
    if (i < BATCH * HID) {
        int b = i >> 9, j = i & 511;
        g_h0v[i] = hst[(b << 10) + j];
        g_h1v[i] = hst[(b << 10) + 512 + j];
    }
}

// C[M,N] = A[M,K] @ B[N,K]^T (+bias). 128x128 tile, BK=16, 8x8 microtile.
__global__ __launch_bounds__(256, 2) void gemm_abt_kernel(
    const float* __restrict__ A, const float* __restrict__ B,
    const float* __restrict__ bias, float* __restrict__ C,
    int M, int N, int K)
{
    __shared__ __align__(16) float As[16][132];
    __shared__ __align__(16) float Bs[16][132];
    const int t = threadIdx.x, tx = t & 15, ty = t >> 4;
    const int m0 = blockIdx.y * 128, n0 = blockIdx.x * 128;
    const float* Ab = A + (size_t)m0 * K;
    const float* Bb = B + (size_t)n0 * K;

    float acc[8][8];
#pragma unroll
    for (int i = 0; i < 8; i++)
#pragma unroll
        for (int j = 0; j < 8; j++) acc[i][j] = 0.0f;

    for (int k0 = 0; k0 < K; k0 += 16) {
#pragma unroll
        for (int u = 0; u < 2; u++) {
            int f = t + 256 * u, r = f >> 2, c4 = f & 3;
            float4 va = *(const float4*)(Ab + (size_t)r * K + k0 + c4 * 4);
            As[c4*4+0][r] = va.x; As[c4*4+1][r] = va.y;
            As[c4*4+2][r] = va.z; As[c4*4+3][r] = va.w;
            float4 vb = *(const float4*)(Bb + (size_t)r * K + k0 + c4 * 4);
            Bs[c4*4+0][r] = vb.x; Bs[c4*4+1][r] = vb.y;
            Bs[c4*4+2][r] = vb.z; Bs[c4*4+3][r] = vb.w;
        }
        __syncthreads();
#pragma unroll
        for (int k = 0; k < 16; k++) {
            float rm[8], rn[8];
            *(float4*)&rm[0] = *(const float4*)&As[k][ty*8];
            *(float4*)&rm[4] = *(const float4*)&As[k][ty*8+4];
            *(float4*)&rn[0] = *(const float4*)&Bs[k][tx*8];
            *(float4*)&rn[4] = *(const float4*)&Bs[k][tx*8+4];
#pragma unroll
            for (int i = 0; i < 8; i++)
#pragma unroll
                for (int j = 0; j < 8; j++)
                    acc[i][j] = fmaf(rm[i], rn[j], acc[i][j]);
        }
        __syncthreads();
    }
    float bv[8];
#pragma unroll
    for (int j = 0; j < 8; j++) bv[j] = bias ? bias[n0 + tx*8 + j] : 0.0f;
#pragma unroll
    for (int i = 0; i < 8; i++) {
        float* cp = C + (size_t)(m0 + ty*8 + i) * N + n0 + tx*8;
        float4 o0, o1;
        o0.x = acc[i][0]+bv[0]; o0.y = acc[i][1]+bv[1];
        o0.z = acc[i][2]+bv[2]; o0.w = acc[i][3]+bv[3];
        o1.x = acc[i][4]+bv[4]; o1.y = acc[i][5]+bv[5];
        o1.z = acc[i][6]+bv[6]; o1.w = acc[i][7]+bv[7];
        *(float4*)cp = o0; *(float4*)(cp+4) = o1;
    }
}

// ---- gang matvec map (8 warps / 256 thr per gang) ----
// warp w8: jh = w8&1, kh = w8>>1 (0..3). lane: jq = lane&7, kq = lane>>3 (0..3).
// j_local = jh*8 + jq (16).  float4 idx f = kq + 4*kh + 16*kk, kk 0..7 (128).
// Weight elements read exactly once per CTA; h broadcasts 8-wide per phase.
// Partials q[kh][b][j_local] = q[kh*64 + b*16 + jl]; final sum over 4 kh.
__device__ __forceinline__ void mv_quad(const float* __restrict__ T,
    const float* __restrict__ w0, const float* __restrict__ w1,
    const float* __restrict__ w2, const float* __restrict__ w3,
    float* q0, float* q1, float* q2, float* q3,
    int jl, int jq, int kq, int kh)
{
    const int fb = (kq + 4*kh) * 4;
    unsigned long long a0[4]={0,0,0,0}, a1[4]={0,0,0,0},
                       a2[4]={0,0,0,0}, a3[4]={0,0,0,0};
#pragma unroll
    for (int kk = 0; kk < 8; kk++) {
        const int fo = fb + kk * 64;
        ulonglong2 wa = *(const ulonglong2*)&w0[jl*HPW + fo];
        ulonglong2 wb = *(const ulonglong2*)&w1[jl*HPW + fo];
        ulonglong2 wc = *(const ulonglong2*)&w2[jl*HPW + fo];
        ulonglong2 wd = *(const ulonglong2*)&w3[jl*HPW + fo];
#pragma unroll
        for (int b = 0; b < 4; b++) {
            ulonglong2 hv = *(const ulonglong2*)&T[b*HPT + fo];
            ffma2(a0[b], hv.x, wa.x); ffma2(a0[b], hv.y, wa.y);
            ffma2(a1[b], hv.x, wb.x); ffma2(a1[b], hv.y, wb.y);
            ffma2(a2[b], hv.x, wc.x); ffma2(a2[b], hv.y, wc.y);
            ffma2(a3[b], hv.x, wd.x); ffma2(a3[b], hv.y, wd.y);
        }
    }
    float s0[4], s1[4], s2[4], s3[4];
#pragma unroll
    for (int b = 0; b < 4; b++) {
        s0[b]=hsum2(a0[b]); s1[b]=hsum2(a1[b]); s2[b]=hsum2(a2[b]); s3[b]=hsum2(a3[b]);
    }
#pragma unroll
    for (int off = 8; off < 32; off <<= 1)
#pragma unroll
        for (int b = 0; b < 4; b++) {
            s0[b] += __shfl_xor_sync(0xffffffffu, s0[b], off);
            s1[b] += __shfl_xor_sync(0xffffffffu, s1[b], off);
            s2[b] += __shfl_xor_sync(0xffffffffu, s2[b], off);
            s3[b] += __shfl_xor_sync(0xffffffffu, s3[b], off);
        }
    if (kq == 0)
#pragma unroll
        for (int b = 0; b < 4; b++) {
            int o = kh*64 + b*16 + jl;
            q0[o] = s0[b]; q1[o] = s1[b]; q2[o] = s2[b]; q3[o] = s3[b];
        }
}
__device__ __forceinline__ void mv_pair(const float* __restrict__ T,
    const float* __restrict__ w0, const float* __restrict__ w1,
    float* q0, float* q1, int jl, int jq, int kq, int kh)
{
    const int fb = (kq + 4*kh) * 4;
    unsigned long long a0[4]={0,0,0,0}, a1[4]={0,0,0,0};
#pragma unroll
    for (int kk = 0; kk < 8; kk++) {
        const int fo = fb + kk * 64;
        ulonglong2 wa = *(const ulonglong2*)&w0[jl*HPW + fo];
        ulonglong2 wb = *(const ulonglong2*)&w1[jl*HPW + fo];
#pragma unroll
        for (int b = 0; b < 4; b++) {
            ulonglong2 hv = *(const ulonglong2*)&T[b*HPT + fo];
            ffma2(a0[b], hv.x, wa.x); ffma2(a0[b], hv.y, wa.y);
            ffma2(a1[b], hv.x, wb.x); ffma2(a1[b], hv.y, wb.y);
        }
    }
    float s0[4], s1[4];
#pragma unroll
    for (int b = 0; b < 4; b++) { s0[b]=hsum2(a0[b]); s1[b]=hsum2(a1[b]); }
#pragma unroll
    for (int off = 8; off < 32; off <<= 1)
#pragma unroll
        for (int b = 0; b < 4; b++) {
            s0[b] += __shfl_xor_sync(0xffffffffu, s0[b], off);
            s1[b] += __shfl_xor_sync(0xffffffffu, s1[b], off);
        }
    if (kq == 0)
#pragma unroll
        for (int b = 0; b < 4; b++) {
            int o = kh*64 + b*16 + jl;
            q0[o] = s0[b]; q1[o] = s1[b];
        }
}
__device__ __forceinline__ void mv_one(const float* __restrict__ T,
    const float* __restrict__ w0, float* q0, int jl, int jq, int kq, int kh)
{
    const int fb = (kq + 4*kh) * 4;
    unsigned long long a0[4]={0,0,0,0};
#pragma unroll
    for (int kk = 0; kk < 8; kk++) {
        const int fo = fb + kk * 64;
        ulonglong2 wa = *(const ulonglong2*)&w0[jl*HPW + fo];
#pragma unroll
        for (int b = 0; b < 4; b++) {
            ulonglong2 hv = *(const ulonglong2*)&T[b*HPT + fo];
            ffma2(a0[b], hv.x, wa.x); ffma2(a0[b], hv.y, wa.y);
        }
    }
    float s0[4];
#pragma unroll
    for (int b = 0; b < 4; b++) s0[b] = hsum2(a0[b]);
#pragma unroll
    for (int off = 8; off < 32; off <<= 1)
#pragma unroll
        for (int b = 0; b < 4; b++)
            s0[b] += __shfl_xor_sync(0xffffffffu, s0[b], off);
    if (kq == 0)
#pragma unroll
        for (int b = 0; b < 4; b++)
            q0[kh*64 + b*16 + jl] = s0[b];
}
__device__ __forceinline__ float q4sum(const float* q, int idx) {
    return (q[idx] + q[64+idx]) + (q[128+idx] + q[192+idx]);
}
// Load pipeline tile: 4 batches x 512 floats = 512 float4; 256 thr x 2.
__device__ __forceinline__ void load_tile(float* T, const float* g, int pipe, int gtid) {
#pragma unroll
    for (int u = 0; u < 2; u++) {
        int f = gtid + 256*u, b = f >> 7, c = f & 127;
        float4 v = __ldcg((const float4*)g + (BL*pipe + b) * 128 + c);
        *(float4*)&T[b*HPT + c*4] = v;
    }
}

// ---- 4 independent pipelines (batch-split), warp-specialized gangs ----
__global__ __launch_bounds__(512, 1) void gru_ws_kernel(
    const float* __restrict__ pz0, const float* __restrict__ pr0,
    const float* __restrict__ Whz0, const float* __restrict__ bhz0,
    const float* __restrict__ Whr0, const float* __restrict__ bhr0,
    const float* __restrict__ Wxz1, const float* __restrict__ Whz1,
    const float* __restrict__ bhz1, const float* __restrict__ Wxr1,
    const float* __restrict__ Whr1, const float* __restrict__ bhr1,
    float* __restrict__ hf)
{
    extern __shared__ float sm[];
    float* wz0  = sm;                    // [16][HPW] x6 weight slices
    float* wr0  = wz0 + JSL*HPW;
    float* wz1  = wr0 + JSL*HPW;
    float* wr1  = wz1 + JSL*HPW;
    float* wxz  = wr1 + JSL*HPW;
    float* wxr  = wxz + JSL*HPW;
    float* T0   = wxr + JSL*HPW;         // [4][HPT] gang0 tile
    float* T1   = T0 + BL*HPT;           // [4][HPT] gang1 tile
    float* q0   = T1 + BL*HPT;           // partials [256] x6
    float* q1   = q0 + 256;
    float* q2   = q1 + 256;
    float* q3   = q2 + 256;
    float* q4   = q3 + 256;
    float* q5   = q4 + 256;
    float* z0s  = q5 + 256;              // [64] each
    float* h0s  = z0s + 64;
    float* xz0s = h0s + 64;
    float* xr0s = xz0s + 64;
    float* z1s  = xr0s + 64;
    float* h1s  = z1s + 64;
    float* axrs = h1s + 64;
    float* axr2 = axrs + 64;             // [2][64] handoff
    float* axz2 = axr2 + 128;            // [2][64]
    float* bz0  = axz2 + 128;            // [16] each
    float* br0  = bz0 + 16;
    float* bz1  = br0 + 16;
    float* br1  = bz1 + 16;
    volatile int* flags = (volatile int*)(br1 + 16);  // [0]=axr ready, [1]=consumed

    const int tid  = threadIdx.x;
    const int gang = tid >> 8;
    const int gtid = tid & 255;
    const int pipe = blockIdx.x >> 5;          // 0..3
    const int jg   = blockIdx.x & 31;          // 0..31
    const int j0g  = jg * JSL;                 // global j base
    const int lane = tid & 31;
    const int w8   = (tid >> 5) & 7;
    const int jq = lane & 7, kq = lane >> 3;
    const int jh = w8 & 1, kh = w8 >> 1;
    const int jl = jh*8 + jq;

    for (int idx = tid; idx < JSL * HID; idx += 512) {
        int jj = idx >> 9, k = idx & 511;
        size_t w = (size_t)(j0g + jj) * HID + k;
        int s = jj * HPW + k;
        wz0[s] = Whz0[w]; wr0[s] = Whr0[w];
        wz1[s] = Whz1[w]; wr1[s] = Whr1[w];
        wxz[s] = Wxz1[w]; wxr[s] = Wxr1[w];
    }
    if (tid < JSL) {
        bz0[tid] = bhz0[j0g+tid]; br0[tid] = bhr0[j0g+tid];
        bz1[tid] = bhz1[j0g+tid]; br1[tid] = bhr1[j0g+tid];
    }
    if (tid == 0) { flags[0] = 0; flags[1] = 0; }
    __syncthreads();

    unsigned int* C_RH0 = &g_ctr[(0*4 + pipe) * 32];
    unsigned int* C_H0  = &g_ctr[(1*4 + pipe) * 32];
    unsigned int* C_RH1 = &g_ctr[(2*4 + pipe) * 32];
    unsigned int* C_H1  = &g_ctr[(3*4 + pipe) * 32];

    if (gang == 0) {
        // ============ layer 0 + layer-1 input projections ============
        unsigned int tgt = PCTAS;
        for (int t = 0; t <= S_LEN; t++) {
            load_tile(T0, g_h0v, pipe, gtid);      // h0 == y0[t-1]
            if (t < S_LEN && gtid < 16) {
                int bl = gtid >> 2, part = gtid & 3;
                size_t off = ((size_t)((BL*pipe + bl) * S_LEN + t) << 9) + j0g + part*4;
                *(float4*)&xz0s[bl*16 + part*4] = *(const float4*)(pz0 + off);
                *(float4*)&xr0s[bl*16 + part*4] = *(const float4*)(pr0 + off);
            }
            barg(1);
            mv_quad(T0, wr0, wz0, wxr, wxz, q0, q1, q2, q3, jl, jq, kq, kh);
            barg(1);
            if (gtid < 64) {
                const int b = gtid >> 4, jj = gtid & 15;
                if (t >= 1) {
                    while (flags[1] < t - 2) { }
                    axr2[(t&1)*64 + gtid] = q4sum(q2, gtid);
                    axz2[(t&1)*64 + gtid] = q4sum(q3, gtid);
                }
                if (t < S_LEN) {
                    float pr = q4sum(q0, gtid) + xr0s[gtid] + br0[jj];
                    float pz = q4sum(q1, gtid) + xz0s[gtid] + bz0[jj];
                    float r  = 1.0f / (1.0f + __expf(-pr));
                    z0s[gtid] = 1.0f / (1.0f + __expf(-pz));
                    float ho = T0[b*HPT + j0g + jj];
                    h0s[gtid] = ho;
                    __stcg(&g_rh0[((BL*pipe + b) << 9) + j0g + jj], r * ho);
                }
            }
            barg(1);
            if (gtid == 0) {
                if (t >= 1) { __threadfence_block(); flags[0] = t; }
                if (t < S_LEN) ctr_rel(C_RH0);
            }
            if (t == S_LEN) break;

            // phase B: g0, h0_new
            if (gtid == 0) ctr_poll(C_RH0, tgt);
            barg(1);
            load_tile(T0, g_rh0, pipe, gtid);
            barg(1);
            mv_one(T0, wr0, q0, jl, jq, kq, kh);
            barg(1);
            if (gtid < 64) {
                const int b = gtid >> 4, jj = gtid & 15;
                float pg = q4sum(q0, gtid) + xr0s[gtid] + br0[jj];
                float g  = tanhf(pg);
                float z  = z0s[gtid];
                float hn = z * h0s[gtid] + (1.0f - z) * g;
                __stcg(&g_h0v[((BL*pipe + b) << 9) + j0g + jj], hn);   // == y0[t]
                if (t == S_LEN - 1) hf[((BL*pipe + b) << 10) + j0g + jj] = hn;
            }
            barg(1);
            if (gtid == 0) { ctr_rel(C_H0); ctr_poll(C_H0, tgt); }
            tgt += PCTAS;
            barg(1);
        }
    } else {
        // ============ layer 1 (GRU step s = t-1) ============
        unsigned int tgt = PCTAS;
        for (int t = 1; t <= S_LEN; t++) {
            load_tile(T1, g_h1v, pipe, gtid);
            barg(2);
            mv_pair(T1, wr1, wz1, q4, q5, jl, jq, kq, kh);
            barg(2);
            if (gtid < 64) {
                const int b = gtid >> 4, jj = gtid & 15;
                while (flags[0] < t) { }
                __threadfence_block();
                float axr = axr2[(t&1)*64 + gtid];
                float axz = axz2[(t&1)*64 + gtid];
                float pr = q4sum(q4, gtid) + axr + br1[jj];
                float pz = q4sum(q5, gtid) + axz + bz1[jj];
                float r  = 1.0f / (1.0f + __expf(-pr));
                z1s[gtid] = 1.0f / (1.0f + __expf(-pz));
                float ho = T1[b*HPT + j0g + jj];
                h1s[gtid] = ho; axrs[gtid] = axr;
                __stcg(&g_rh1[((BL*pipe + b) << 9) + j0g + jj], r * ho);
            }
            barg(2);
            if (gtid == 0) {
                flags[1] = t;
                ctr_rel(C_RH1); ctr_poll(C_RH1, tgt);
            }
            barg(2);
            load_tile(T1, g_rh1, pipe, gtid);
            barg(2);
            mv_one(T1, wr1, q4, jl, jq, kq, kh);
            barg(2);
            if (gtid < 64) {
                const int b = gtid >> 4, jj = gtid & 15;
                float pg = q4sum(q4, gtid) + axrs[gtid] + br1[jj];
                float g  = tanhf(pg);
                float z  = z1s[gtid];
                float hn = z * h1s[gtid] + (1.0f - z) * g;
                __stcg(&g_h1v[((BL*pipe + b) << 9) + j0g + jj], hn);
                g_y1[((size_t)((BL*pipe + b) * S_LEN + (t-1)) << 9) + j0g + jj] = hn;
                if (t == S_LEN) hf[((BL*pipe + b) << 10) + 512 + j0g + jj] = hn;
            }
            barg(2);
            if (gtid == 0) { ctr_rel(C_H1); ctr_poll(C_H1, tgt); }
            tgt += PCTAS;
            barg(2);
        }
    }
}

extern "C" void kernel_launch(void* const* d_in, const int* in_sizes, int n_in,
                              void* d_out, int out_size)
{
    (void)in_sizes; (void)n_in; (void)out_size;
    const float* x    = (const float*)d_in[0];
    const float* hst  = (const float*)d_in[1];
    const float* Wxz0 = (const float*)d_in[2];
    const float* Whz0 = (const float*)d_in[3];
    const float* bhz0 = (const float*)d_in[4];
    const float* Wxr0 = (const float*)d_in[5];
    const float* Whr0 = (const float*)d_in[6];
    const float* bhr0 = (const float*)d_in[7];
    const float* Wxz1 = (const float*)d_in[8];
    const float* Whz1 = (const float*)d_in[9];
    const float* bhz1 = (const float*)d_in[10];
    const float* Wxr1 = (const float*)d_in[11];
    const float* Whr1 = (const float*)d_in[12];
    const float* bhr1 = (const float*)d_in[13];
    const float* Why  = (const float*)d_in[14];
    const float* by   = (const float*)d_in[15];
    float* out = (float*)d_out;

    float *pz, *pr, *y1;
    cudaGetSymbolAddress((void**)&pz, g_pz);
    cudaGetSymbolAddress((void**)&pr, g_pr);
    cudaGetSymbolAddress((void**)&y1, g_y1);

    const int GRU_SMEM = (6*JSL*HPW + 2*BL*HPT + 6*256 + 7*64 + 2*128 + 4*16 + 8) * 4;
    cudaFuncSetAttribute(gru_ws_kernel,
                         cudaFuncAttributeMaxDynamicSharedMemorySize, GRU_SMEM);

    const int M = BATCH * S_LEN;                        // 32768
    float* hf = out + (size_t)BATCH * S_LEN * OUT_DIM;  // h_final [B,2,H]

    // layer-0 input projections (K = 128), off the critical path
    gemm_abt_kernel<<<dim3(HID/128, M/128), 256>>>(x, Wxz0, nullptr, pz, M, HID, IN_DIM);
    gemm_abt_kernel<<<dim3(HID/128, M/128), 256>>>(x, Wxr0, nullptr, pr, M, HID, IN_DIM);
    init_kernel<<<32, 256>>>(hst);

    // batch-split pipelined recurrence (4 independent 32-CTA pipelines)
    gru_ws_kernel<<<NPIPE * PCTAS, 512, GRU_SMEM>>>(pz, pr,
        Whz0, bhz0, Whr0, bhr0,
        Wxz1, Whz1, bhz1, Wxr1, Whr1, bhr1, hf);

    // output head: out = y1 @ Why^T + by
    gemm_abt_kernel<<<dim3(OUT_DIM/128, M/128), 256>>>(y1, Why, by, out, M, OUT_DIM, HID);
}